// round 4
// baseline (speedup 1.0000x reference)
#include <cuda_runtime.h>
#include <cuda_bf16.h>
#include <cstdint>

#define BQ 4096
#define DD 256
#define KK 65536
#define TM 128
#define TN 128
#define NCHUNK 512          // KK / TN
#define NMTILE 32           // BQ / TM
#define MAIN_GRID 148
#define NTHREADS 512
#define MARGIN 8.0f
#define QSCALE 16.0f
#define CAND_CAP (1u << 22)

#define AP 272                          // smem row pitch bytes (256 data + 16 pad)
#define ABYTES (128 * AP)               // 34816
#define SM_A   0
#define SM_B0  ABYTES
#define SM_B1  (2 * ABYTES)
#define SMEM_TOTAL (3 * ABYTES)         // 104448 bytes

__device__ signed char g_cent8[(size_t)KK * DD];      // 16 MB
__device__ signed char g_x8[(size_t)BQ * DD];         // 1 MB
__device__ float              g_csq[KK];
__device__ unsigned long long g_packed[BQ];           // approx best (fkey<<32)|idx
__device__ unsigned long long g_final[BQ];            // exact best among candidates
__device__ unsigned           g_ncand;
__device__ unsigned           g_cand[CAND_CAP];       // (row<<16)|col

__device__ __forceinline__ unsigned fkey(float f) {
    unsigned u = __float_as_uint(f);
    return (u & 0x80000000u) ? ~u : (u | 0x80000000u);
}
__device__ __forceinline__ float unfkey(unsigned k) {
    unsigned u = (k & 0x80000000u) ? (k ^ 0x80000000u) : ~k;
    return __uint_as_float(u);
}
__device__ __forceinline__ unsigned smem_u32(const void* p) {
    unsigned a;
    asm("{ .reg .u64 t; cvta.to.shared.u64 t, %1; cvt.u32.u64 %0, t; }"
        : "=r"(a) : "l"(p));
    return a;
}
__device__ __forceinline__ void ldsm_x4(unsigned* r, unsigned addr) {
    asm volatile("ldmatrix.sync.aligned.m8n8.x4.shared.b16 {%0,%1,%2,%3},[%4];"
                 : "=r"(r[0]), "=r"(r[1]), "=r"(r[2]), "=r"(r[3]) : "r"(addr));
}
__device__ __forceinline__ void mma_s8(int* c, const unsigned* a,
                                       const unsigned* b) {
    asm volatile(
        "mma.sync.aligned.m16n8k32.row.col.s32.s8.s8.s32 "
        "{%0,%1,%2,%3},{%4,%5,%6,%7},{%8,%9},{%0,%1,%2,%3};"
        : "+r"(c[0]), "+r"(c[1]), "+r"(c[2]), "+r"(c[3])
        : "r"(a[0]), "r"(a[1]), "r"(a[2]), "r"(a[3]), "r"(b[0]), "r"(b[1]));
}
__device__ __forceinline__ signed char quant1(float f) {
    int t = __float2int_rn(f * QSCALE);
    t = max(-127, min(127, t));
    return (signed char)t;
}

// ---------------------------------------------------------------------------
__global__ void init_kernel() {
    int i = blockIdx.x * blockDim.x + threadIdx.x;
    if (i < BQ) {
        g_packed[i] = 0xFFFFFFFFFFFFFFFFull;
        g_final[i]  = 0xFFFFFFFFFFFFFFFFull;
    }
    if (i == 0) g_ncand = 0u;
}

__global__ void csq_kernel(const float* __restrict__ cent) {
    int warp = threadIdx.x >> 5, lane = threadIdx.x & 31;
    int c = blockIdx.x * 8 + warp;
    const float4* p = (const float4*)(cent + (size_t)c * DD);
    float s = 0.f;
#pragma unroll
    for (int i = 0; i < 2; i++) {
        float4 v = p[lane + 32 * i];
        s = fmaf(v.x, v.x, s); s = fmaf(v.y, v.y, s);
        s = fmaf(v.z, v.z, s); s = fmaf(v.w, v.w, s);
    }
#pragma unroll
    for (int o = 16; o > 0; o >>= 1) s += __shfl_xor_sync(0xffffffffu, s, o);
    if (lane == 0) g_csq[c] = s;
}

__global__ void cvt_cent_kernel(const float* __restrict__ cent) {
    size_t i = (size_t)blockIdx.x * blockDim.x + threadIdx.x;  // float4 units
    float4 v = ((const float4*)cent)[i];
    char4 q;
    q.x = quant1(v.x); q.y = quant1(v.y); q.z = quant1(v.z); q.w = quant1(v.w);
    ((char4*)g_cent8)[i] = q;
}
__global__ void cvt_x_kernel(const float* __restrict__ x) {
    size_t i = (size_t)blockIdx.x * blockDim.x + threadIdx.x;
    float4 v = ((const float4*)x)[i];
    char4 q;
    q.x = quant1(v.x); q.y = quant1(v.y); q.z = quant1(v.z); q.w = quant1(v.w);
    ((char4*)g_x8)[i] = q;
}

// ---------------------------------------------------------------------------
__device__ __forceinline__ void load_B_async(unsigned bb, int chunk, int tid) {
    const char* src = (const char*)(g_cent8 + (size_t)chunk * TN * DD);
#pragma unroll
    for (int i = 0; i < 4; i++) {
        int j = i * NTHREADS + tid;          // 2048 16B ops
        int col = j >> 4, seg = j & 15;
        unsigned dst = bb + (unsigned)col * AP + (unsigned)seg * 16u;
        const void* gp = src + (size_t)col * 256 + seg * 16;
        asm volatile("cp.async.cg.shared.global [%0], [%1], 16;"
                     :: "r"(dst), "l"(gp));
    }
}

__device__ __forceinline__ void load_A(char* smem, int mtile, int tid) {
    const char* src = (const char*)(g_x8 + (size_t)mtile * TM * DD);
#pragma unroll
    for (int i = 0; i < 4; i++) {
        int j = i * NTHREADS + tid;
        int row = j >> 4, seg = j & 15;
        uint4 v = *(const uint4*)(src + (size_t)row * 256 + seg * 16);
        *(uint4*)(smem + SM_A + row * AP + seg * 16) = v;
    }
}

__device__ __forceinline__ void flush_best(const float* bestV, const int* bestI,
                                           int rowBase, int lane) {
#pragma unroll
    for (int r = 0; r < 4; r++) {     // r = mi*2 + half
        unsigned long long p =
            ((unsigned long long)fkey(bestV[r]) << 32) | (unsigned)bestI[r];
        unsigned long long q;
        q = __shfl_xor_sync(0xffffffffu, p, 1); if (q < p) p = q;
        q = __shfl_xor_sync(0xffffffffu, p, 2); if (q < p) p = q;
        if ((lane & 3) == 0) {
            int row = rowBase + (r >> 1) * 16 + (r & 1) * 8 + (lane >> 2);
            atomicMin(&g_packed[row], p);
        }
    }
}

__global__ void __launch_bounds__(NTHREADS, 1) main_kernel() {
    extern __shared__ char smem[];
    const unsigned sbase = smem_u32(smem);
    const int tid = threadIdx.x;
    const int wid = tid >> 5, lane = tid & 31;
    const int wr = wid >> 2, wc = wid & 3;   // warp 32x32 tile at (wr*32, wc*32)

    const long total = (long)NMTILE * NCHUNK;
    const long s = (long)blockIdx.x * total / MAIN_GRID;
    const long e = (long)(blockIdx.x + 1) * total / MAIN_GRID;
    const int T = (int)(e - s);

    // ldmatrix addresses: lane-group g = lane>>3
    // A frag (m16k32): rows0-7/+0, rows8-15/+0, rows0-7/+16, rows8-15/+16
    unsigned aAddr[2];
#pragma unroll
    for (int mi = 0; mi < 2; mi++) {
        int row = wr * 32 + mi * 16 + ((lane >> 3) & 1) * 8 + (lane & 7);
        aAddr[mi] = sbase + SM_A + (unsigned)(row * AP + (lane >> 4) * 16);
    }
    // B frag pair (two n8 blocks per ldsm.x4): cols+0/+0, +0/+16, +8/+0, +8/+16
    unsigned bOfs[2];
#pragma unroll
    for (int pr = 0; pr < 2; pr++) {
        int col = wc * 32 + pr * 16 + ((lane >> 4) << 3) + (lane & 7);
        bOfs[pr] = (unsigned)(col * AP + ((lane >> 3) & 1) * 16);
    }

    float bestV[4];
    int   bestI[4];
#pragma unroll
    for (int r = 0; r < 4; r++) { bestV[r] = 3.4e38f; bestI[r] = 0; }

    int cur_m = (int)(s >> 9);
    load_A(smem, cur_m, tid);
    load_B_async(sbase + SM_B0, (int)(s & 511), tid);
    asm volatile("cp.async.commit_group;" ::: "memory");

    for (int i = 0; i < T; i++) {
        const long u = s + i;
        const int mt = (int)(u >> 9);
        const int chunk = (int)(u & 511);
        const unsigned bbase = sbase + (unsigned)((i & 1) ? SM_B1 : SM_B0);

        __syncthreads();   // everyone done with A / the B buffer being refilled
        if (mt != cur_m) {
            flush_best(bestV, bestI, cur_m * TM + wr * 32, lane);
#pragma unroll
            for (int r = 0; r < 4; r++) { bestV[r] = 3.4e38f; bestI[r] = 0; }
            load_A(smem, mt, tid);
            cur_m = mt;
        }
        if (i + 1 < T) {
            load_B_async(sbase + (unsigned)(((i + 1) & 1) ? SM_B1 : SM_B0),
                         (int)((u + 1) & 511), tid);
            asm volatile("cp.async.commit_group;" ::: "memory");
            asm volatile("cp.async.wait_group 1;" ::: "memory");
        } else {
            asm volatile("cp.async.wait_group 0;" ::: "memory");
        }
        __syncthreads();   // B(i) visible

        // ---- int8 GEMM: CTA 128x128x256, warp 32x32 ----
        int acc[2][4][4];
#pragma unroll
        for (int mi = 0; mi < 2; mi++)
#pragma unroll
            for (int nf = 0; nf < 4; nf++)
#pragma unroll
                for (int c = 0; c < 4; c++) acc[mi][nf][c] = 0;

#pragma unroll
        for (int k = 0; k < 8; k++) {     // k32 steps
            unsigned a[2][4], b[2][4];
#pragma unroll
            for (int mi = 0; mi < 2; mi++)
                ldsm_x4(a[mi], aAddr[mi] + (unsigned)(k * 32));
#pragma unroll
            for (int pr = 0; pr < 2; pr++)
                ldsm_x4(b[pr], bbase + bOfs[pr] + (unsigned)(k * 32));
#pragma unroll
            for (int mi = 0; mi < 2; mi++)
#pragma unroll
                for (int nf = 0; nf < 4; nf++)
                    mma_s8(acc[mi][nf], a[mi], &b[nf >> 1][(nf & 1) * 2]);
        }

        // ---- epilogue: dist = csq - 2*dot/256, argmin + margin capture ----
        const int col0 = chunk * TN + wc * 32 + 2 * (lane & 3);
        float q[4][2];
#pragma unroll
        for (int nf = 0; nf < 4; nf++) {
            q[nf][0] = __ldg(&g_csq[col0 + nf * 8]);
            q[nf][1] = __ldg(&g_csq[col0 + nf * 8 + 1]);
        }
#pragma unroll
        for (int mi = 0; mi < 2; mi++)
#pragma unroll
            for (int half = 0; half < 2; half++) {
                const int rIdx = mi * 2 + half;
                const int row_g = mt * TM + wr * 32 + mi * 16 + half * 8 + (lane >> 2);
                unsigned long long snap = g_packed[row_g];
                unsigned sk = (unsigned)(snap >> 32);
                float bound = fminf(
                    (sk == 0xFFFFFFFFu) ? 3.4e38f : unfkey(sk),
                    bestV[rIdx]) + MARGIN;
                float bv = bestV[rIdx];
                int   bi = bestI[rIdx];
#pragma unroll
                for (int nf = 0; nf < 4; nf++)
#pragma unroll
                    for (int cc = 0; cc < 2; cc++) {
                        float dist = fmaf(-0.0078125f,
                                          (float)acc[mi][nf][half * 2 + cc],
                                          q[nf][cc]);
                        int col = col0 + nf * 8 + cc;
                        if (dist <= bound) {
                            unsigned slot = atomicAdd(&g_ncand, 1u);
                            if (slot < CAND_CAP)
                                g_cand[slot] = ((unsigned)row_g << 16) |
                                               (unsigned)col;
                        }
                        bound = fminf(bound, dist + MARGIN);
                        if (dist < bv) { bv = dist; bi = col; }
                    }
                bestV[rIdx] = bv;
                bestI[rIdx] = bi;
            }
    }
    flush_best(bestV, bestI, cur_m * TM + wr * 32, lane);
}

// ---------------------------------------------------------------------------
// Exact fp32 rescore of captured candidates
// ---------------------------------------------------------------------------
__global__ void rescore_kernel(const float* __restrict__ x,
                               const float* __restrict__ cent) {
    unsigned n = g_ncand;
    if (n > CAND_CAP) n = CAND_CAP;
    int gw = (blockIdx.x * blockDim.x + threadIdx.x) >> 5;
    int lane = threadIdx.x & 31;
    int nw = (gridDim.x * blockDim.x) >> 5;
    for (unsigned eidx = gw; eidx < n; eidx += nw) {
        unsigned ent = g_cand[eidx];
        unsigned row = ent >> 16;
        unsigned col = ent & 0xFFFFu;
        const float4* xp = (const float4*)(x + (size_t)row * DD);
        const float4* cp = (const float4*)(cent + (size_t)col * DD);
        float sdot = 0.f;
#pragma unroll
        for (int i = 0; i < 2; i++) {
            float4 a = xp[lane + 32 * i];
            float4 b = cp[lane + 32 * i];
            sdot = fmaf(a.x, b.x, sdot); sdot = fmaf(a.y, b.y, sdot);
            sdot = fmaf(a.z, b.z, sdot); sdot = fmaf(a.w, b.w, sdot);
        }
#pragma unroll
        for (int o = 16; o > 0; o >>= 1)
            sdot += __shfl_xor_sync(0xffffffffu, sdot, o);
        if (lane == 0) {
            float dist = fmaf(-2.0f, sdot, __ldg(&g_csq[col]));
            atomicMin(&g_final[row],
                      ((unsigned long long)fkey(dist) << 32) | col);
        }
    }
}

// ---------------------------------------------------------------------------
__global__ void finalize_kernel(const float* __restrict__ cent,
                                float* __restrict__ out_xhat,
                                float* __restrict__ out_codes) {
    int warp = threadIdx.x >> 5, lane = threadIdx.x & 31;
    int row = blockIdx.x * 8 + warp;
    if (row >= BQ) return;
    unsigned idx = (unsigned)(g_final[row] & 0xFFFFFFFFull);
    if (out_xhat) {
        const float4* src = (const float4*)(cent + (size_t)idx * DD);
        float4* dst = (float4*)(out_xhat + (size_t)row * DD);
        dst[lane] = src[lane];
        dst[lane + 32] = src[lane + 32];
    }
    if (out_codes && lane == 0) out_codes[row] = (float)idx;
}

// ---------------------------------------------------------------------------
extern "C" void kernel_launch(void* const* d_in, const int* in_sizes, int n_in,
                              void* d_out, int out_size) {
    const float* x = (const float*)d_in[1];
    const float* cent = (const float*)d_in[2];

    float* out = (float*)d_out;
    float* out_xhat = nullptr;
    float* out_codes = nullptr;
    const int XH = BQ * DD;
    if (out_size >= XH) {
        out_xhat = out;
        if (out_size >= XH + BQ) out_codes = out + XH;
    } else if (out_size >= BQ) {
        out_codes = out;
    }

    cudaFuncSetAttribute(main_kernel,
                         cudaFuncAttributeMaxDynamicSharedMemorySize, SMEM_TOTAL);

    init_kernel<<<(BQ + 255) / 256, 256>>>();
    csq_kernel<<<KK / 8, 256>>>(cent);
    cvt_cent_kernel<<<(KK * DD / 4) / 256, 256>>>(cent);
    cvt_x_kernel<<<(BQ * DD / 4) / 256, 256>>>(x);
    main_kernel<<<MAIN_GRID, NTHREADS, SMEM_TOTAL>>>();
    rescore_kernel<<<512, 256>>>(x, cent);
    finalize_kernel<<<BQ / 8, 256>>>(cent, out_xhat, out_codes);
}

// round 6
// speedup vs baseline: 1.5746x; 1.5746x over previous
#include <cuda_runtime.h>
#include <cuda_bf16.h>
#include <cstdint>

#define BQ 4096
#define DD 256
#define KK 65536
#define TM 128
#define TN 128
#define NCHUNK 512          // KK / TN
#define NMTILE 32           // BQ / TM
#define MAIN_GRID 148
#define NTHREADS 512
#define MARGIN 1.0f
#define CAND_CAP (1u << 22)

#define APITCH 264                      // row pitch in bf16 (528 B)
#define ABYTES (128 * APITCH * 2)       // 67584
#define SM_A   0
#define SM_B0  ABYTES
#define SM_B1  (2 * ABYTES)
#define SMEM_TOTAL (3 * ABYTES)         // 202752 bytes

__device__ __nv_bfloat16 g_cent16[(size_t)KK * DD];   // 32 MB
__device__ __nv_bfloat16 g_x16[(size_t)BQ * DD];      // 2 MB
__device__ float              g_csq[KK];
__device__ unsigned long long g_packed[BQ];           // approx best (fkey<<32)|idx
__device__ unsigned long long g_final[BQ];            // exact best among candidates
__device__ unsigned           g_ncand;
__device__ unsigned           g_cand[CAND_CAP];       // (row<<16)|col

__device__ __forceinline__ unsigned fkey(float f) {
    unsigned u = __float_as_uint(f);
    return (u & 0x80000000u) ? ~u : (u | 0x80000000u);
}
__device__ __forceinline__ float unfkey(unsigned k) {
    unsigned u = (k & 0x80000000u) ? (k ^ 0x80000000u) : ~k;
    return __uint_as_float(u);
}
__device__ __forceinline__ unsigned smem_u32(const void* p) {
    unsigned a;
    asm("{ .reg .u64 t; cvta.to.shared.u64 t, %1; cvt.u32.u64 %0, t; }"
        : "=r"(a) : "l"(p));
    return a;
}
__device__ __forceinline__ void ldsm_x4(unsigned* r, unsigned addr) {
    asm volatile("ldmatrix.sync.aligned.m8n8.x4.shared.b16 {%0,%1,%2,%3},[%4];"
                 : "=r"(r[0]), "=r"(r[1]), "=r"(r[2]), "=r"(r[3]) : "r"(addr));
}
__device__ __forceinline__ void mma_bf16(float* c, const unsigned* a,
                                         const unsigned* b) {
    asm volatile(
        "mma.sync.aligned.m16n8k16.row.col.f32.bf16.bf16.f32 "
        "{%0,%1,%2,%3},{%4,%5,%6,%7},{%8,%9},{%0,%1,%2,%3};"
        : "+f"(c[0]), "+f"(c[1]), "+f"(c[2]), "+f"(c[3])
        : "r"(a[0]), "r"(a[1]), "r"(a[2]), "r"(a[3]), "r"(b[0]), "r"(b[1]));
}

// ---------------------------------------------------------------------------
__global__ void init_kernel() {
    int i = blockIdx.x * blockDim.x + threadIdx.x;
    if (i < BQ) {
        g_packed[i] = 0xFFFFFFFFFFFFFFFFull;
        g_final[i]  = 0xFFFFFFFFFFFFFFFFull;
    }
    if (i == 0) g_ncand = 0u;
}

__global__ void csq_kernel(const float* __restrict__ cent) {
    int warp = threadIdx.x >> 5, lane = threadIdx.x & 31;
    int c = blockIdx.x * 8 + warp;
    const float4* p = (const float4*)(cent + (size_t)c * DD);
    float s = 0.f;
#pragma unroll
    for (int i = 0; i < 2; i++) {
        float4 v = p[lane + 32 * i];
        s = fmaf(v.x, v.x, s); s = fmaf(v.y, v.y, s);
        s = fmaf(v.z, v.z, s); s = fmaf(v.w, v.w, s);
    }
#pragma unroll
    for (int o = 16; o > 0; o >>= 1) s += __shfl_xor_sync(0xffffffffu, s, o);
    if (lane == 0) g_csq[c] = s;
}

__global__ void cvt_cent_kernel(const float* __restrict__ cent) {
    size_t i = (size_t)blockIdx.x * blockDim.x + threadIdx.x;  // float4 units
    float4 v = ((const float4*)cent)[i];
    ((__nv_bfloat162*)g_cent16)[2 * i]     = __floats2bfloat162_rn(v.x, v.y);
    ((__nv_bfloat162*)g_cent16)[2 * i + 1] = __floats2bfloat162_rn(v.z, v.w);
}
__global__ void cvt_x_kernel(const float* __restrict__ x) {
    size_t i = (size_t)blockIdx.x * blockDim.x + threadIdx.x;
    float4 v = ((const float4*)x)[i];
    ((__nv_bfloat162*)g_x16)[2 * i]     = __floats2bfloat162_rn(v.x, v.y);
    ((__nv_bfloat162*)g_x16)[2 * i + 1] = __floats2bfloat162_rn(v.z, v.w);
}

// ---------------------------------------------------------------------------
__device__ __forceinline__ void load_B_async(unsigned bb, int chunk, int tid) {
    const char* src = (const char*)(g_cent16 + (size_t)chunk * TN * DD);
#pragma unroll
    for (int i = 0; i < 8; i++) {
        int j = i * NTHREADS + tid;      // 4096 16B transfers
        int col = j >> 5, seg = j & 31;
        unsigned dst = bb + (unsigned)col * 528u + (unsigned)seg * 16u;
        const void* gp = src + (size_t)col * 512 + seg * 16;
        asm volatile("cp.async.cg.shared.global [%0], [%1], 16;"
                     :: "r"(dst), "l"(gp));
    }
}

__device__ __forceinline__ void load_A(char* smem, int mtile, int tid) {
    const char* src = (const char*)(g_x16 + (size_t)mtile * TM * DD);
#pragma unroll
    for (int i = 0; i < 8; i++) {
        int j = i * NTHREADS + tid;
        int row = j >> 5, seg = j & 31;
        uint4 v = *(const uint4*)(src + (size_t)row * 512 + seg * 16);
        *(uint4*)(smem + SM_A + row * 528 + seg * 16) = v;
    }
}

__device__ __forceinline__ void flush_best(const float* bestV, const int* bestI,
                                           int rowBase, int lane) {
#pragma unroll
    for (int r = 0; r < 4; r++) {     // r = mi*2 + half
        unsigned long long p =
            ((unsigned long long)fkey(bestV[r]) << 32) | (unsigned)bestI[r];
        unsigned long long q;
        q = __shfl_xor_sync(0xffffffffu, p, 1); if (q < p) p = q;
        q = __shfl_xor_sync(0xffffffffu, p, 2); if (q < p) p = q;
        if ((lane & 3) == 0) {
            int row = rowBase + (r >> 1) * 16 + (r & 1) * 8 + (lane >> 2);
            atomicMin(&g_packed[row], p);
        }
    }
}

__device__ __forceinline__ void load_snap(float* snapB, int rowBase, int lane) {
#pragma unroll
    for (int r = 0; r < 4; r++) {
        int row = rowBase + (r >> 1) * 16 + (r & 1) * 8 + (lane >> 2);
        unsigned sk = (unsigned)(g_packed[row] >> 32);
        snapB[r] = (sk == 0xFFFFFFFFu) ? 3.4e38f : unfkey(sk);
    }
}

__global__ void __launch_bounds__(NTHREADS, 1) main_kernel() {
    extern __shared__ char smem[];
    const unsigned sbase = smem_u32(smem);
    const int tid = threadIdx.x;
    const int wid = tid >> 5, lane = tid & 31;
    const int wr = wid >> 2, wc = wid & 3;   // warp 32x32 tile

    const long total = (long)NMTILE * NCHUNK;
    const long s = (long)blockIdx.x * total / MAIN_GRID;
    const long e = (long)(blockIdx.x + 1) * total / MAIN_GRID;
    const int T = (int)(e - s);

    // A frag addresses: lanes0-15 rows0-15 @+0B, lanes16-31 rows0-15 @+16B
    unsigned aAddr[2];
#pragma unroll
    for (int mi = 0; mi < 2; mi++)
        aAddr[mi] = sbase + SM_A +
                    (unsigned)((wr * 32 + mi * 16 + (lane & 15)) * 528 +
                               (lane >> 4) * 16);
    // B frag pair: lanes0-7 n0-7@+0, 8-15 n0-7@+16B, 16-23 n8-15@+0, 24-31 n8-15@+16B
    unsigned bOfs[2];
#pragma unroll
    for (int pr = 0; pr < 2; pr++) {
        int col = wc * 32 + pr * 16 + ((lane >> 4) << 3) + (lane & 7);
        bOfs[pr] = (unsigned)(col * 528 + ((lane >> 3) & 1) * 16);
    }

    float bestV[4];
    int   bestI[4];
    float snapB[4];
#pragma unroll
    for (int r = 0; r < 4; r++) { bestV[r] = 3.4e38f; bestI[r] = 0; }

    int cur_m = (int)(s >> 9);
    load_A(smem, cur_m, tid);
    load_snap(snapB, cur_m * TM + wr * 32, lane);
    load_B_async(sbase + SM_B0, (int)(s & 511), tid);
    asm volatile("cp.async.commit_group;" ::: "memory");

    for (int i = 0; i < T; i++) {
        const long u = s + i;
        const int mt = (int)(u >> 9);
        const int chunk = (int)(u & 511);
        const unsigned bbase = sbase + (unsigned)((i & 1) ? SM_B1 : SM_B0);

        __syncthreads();   // done with A / the B buffer being refilled
        if (mt != cur_m) {
            flush_best(bestV, bestI, cur_m * TM + wr * 32, lane);
#pragma unroll
            for (int r = 0; r < 4; r++) { bestV[r] = 3.4e38f; bestI[r] = 0; }
            load_A(smem, mt, tid);
            load_snap(snapB, mt * TM + wr * 32, lane);
            cur_m = mt;
        }
        if (i + 1 < T) {
            load_B_async(sbase + (unsigned)(((i + 1) & 1) ? SM_B1 : SM_B0),
                         (int)((u + 1) & 511), tid);
            asm volatile("cp.async.commit_group;" ::: "memory");
            asm volatile("cp.async.wait_group 1;" ::: "memory");
        } else {
            asm volatile("cp.async.wait_group 0;" ::: "memory");
        }
        __syncthreads();   // B(i) visible

        // ---- bf16 GEMM: CTA 128x128x256, warp 32x32 ----
        float acc[2][4][4];
#pragma unroll
        for (int mi = 0; mi < 2; mi++)
#pragma unroll
            for (int nf = 0; nf < 4; nf++)
#pragma unroll
                for (int c = 0; c < 4; c++) acc[mi][nf][c] = 0.f;

#pragma unroll
        for (int k16 = 0; k16 < 16; k16++) {
            unsigned a[2][4], b[2][4];
#pragma unroll
            for (int mi = 0; mi < 2; mi++)
                ldsm_x4(a[mi], aAddr[mi] + (unsigned)(k16 * 32));
#pragma unroll
            for (int pr = 0; pr < 2; pr++)
                ldsm_x4(b[pr], bbase + bOfs[pr] + (unsigned)(k16 * 32));
#pragma unroll
            for (int mi = 0; mi < 2; mi++)
#pragma unroll
                for (int pr = 0; pr < 2; pr++) {
                    mma_bf16(acc[mi][pr * 2],     a[mi], &b[pr][0]);
                    mma_bf16(acc[mi][pr * 2 + 1], a[mi], &b[pr][2]);
                }
        }

        // ---- epilogue pass 1: dist in-place, update running best ----
        const int col0 = chunk * TN + wc * 32 + 2 * (lane & 3);
        float q[4][2];
#pragma unroll
        for (int nf = 0; nf < 4; nf++) {
            q[nf][0] = __ldg(&g_csq[col0 + nf * 8]);
            q[nf][1] = __ldg(&g_csq[col0 + nf * 8 + 1]);
        }
#pragma unroll
        for (int mi = 0; mi < 2; mi++)
#pragma unroll
            for (int half = 0; half < 2; half++) {
                const int rIdx = mi * 2 + half;
                float bv = bestV[rIdx];
                int   bi = bestI[rIdx];
#pragma unroll
                for (int nf = 0; nf < 4; nf++)
#pragma unroll
                    for (int cc = 0; cc < 2; cc++) {
                        float d = fmaf(-2.0f, acc[mi][nf][half * 2 + cc],
                                       q[nf][cc]);
                        acc[mi][nf][half * 2 + cc] = d;
                        if (d < bv) { bv = d; bi = col0 + nf * 8 + cc; }
                    }
                bestV[rIdx] = bv;
                bestI[rIdx] = bi;
            }

        // ---- epilogue pass 2: margin capture (warp-aggregated atomics).
        //      All collectives execute in warp-uniform control flow. ----
#pragma unroll
        for (int mi = 0; mi < 2; mi++)
#pragma unroll
            for (int half = 0; half < 2; half++) {
                const int rIdx = mi * 2 + half;
                const float bound =
                    fminf(snapB[rIdx], bestV[rIdx]) + MARGIN;
                const int row_g =
                    cur_m * TM + wr * 32 + mi * 16 + half * 8 + (lane >> 2);
#pragma unroll
                for (int nf = 0; nf < 4; nf++)
#pragma unroll
                    for (int cc = 0; cc < 2; cc++) {
                        bool cap = acc[mi][nf][half * 2 + cc] <= bound;
                        unsigned mask = __ballot_sync(0xffffffffu, cap);
                        if (mask) {                     // uniform branch
                            int leader = __ffs(mask) - 1;
                            unsigned base = 0;
                            if (lane == leader)
                                base = atomicAdd(&g_ncand,
                                                 (unsigned)__popc(mask));
                            base = __shfl_sync(0xffffffffu, base, leader);
                            if (cap) {
                                unsigned slot =
                                    base +
                                    (unsigned)__popc(mask & ((1u << lane) - 1u));
                                if (slot < CAND_CAP)
                                    g_cand[slot] =
                                        ((unsigned)row_g << 16) |
                                        (unsigned)(col0 + nf * 8 + cc);
                            }
                        }
                    }
            }
    }
    flush_best(bestV, bestI, cur_m * TM + wr * 32, lane);
}

// ---------------------------------------------------------------------------
// Exact fp32 rescore of captured candidates
// ---------------------------------------------------------------------------
__global__ void rescore_kernel(const float* __restrict__ x,
                               const float* __restrict__ cent) {
    unsigned n = g_ncand;
    if (n > CAND_CAP) n = CAND_CAP;
    int gw = (blockIdx.x * blockDim.x + threadIdx.x) >> 5;
    int lane = threadIdx.x & 31;
    int nw = (gridDim.x * blockDim.x) >> 5;
    for (unsigned eidx = gw; eidx < n; eidx += nw) {
        unsigned ent = g_cand[eidx];
        unsigned row = ent >> 16;
        unsigned col = ent & 0xFFFFu;
        const float4* xp = (const float4*)(x + (size_t)row * DD);
        const float4* cp = (const float4*)(cent + (size_t)col * DD);
        float sdot = 0.f;
#pragma unroll
        for (int i = 0; i < 2; i++) {
            float4 a = xp[lane + 32 * i];
            float4 b = cp[lane + 32 * i];
            sdot = fmaf(a.x, b.x, sdot); sdot = fmaf(a.y, b.y, sdot);
            sdot = fmaf(a.z, b.z, sdot); sdot = fmaf(a.w, b.w, sdot);
        }
#pragma unroll
        for (int o = 16; o > 0; o >>= 1)
            sdot += __shfl_xor_sync(0xffffffffu, sdot, o);
        if (lane == 0) {
            float dist = fmaf(-2.0f, sdot, __ldg(&g_csq[col]));
            atomicMin(&g_final[row],
                      ((unsigned long long)fkey(dist) << 32) | col);
        }
    }
}

// ---------------------------------------------------------------------------
__global__ void finalize_kernel(const float* __restrict__ cent,
                                float* __restrict__ out_xhat,
                                float* __restrict__ out_codes) {
    int warp = threadIdx.x >> 5, lane = threadIdx.x & 31;
    int row = blockIdx.x * 8 + warp;
    if (row >= BQ) return;
    unsigned idx = (unsigned)(g_final[row] & 0xFFFFFFFFull);
    if (out_xhat) {
        const float4* src = (const float4*)(cent + (size_t)idx * DD);
        float4* dst = (float4*)(out_xhat + (size_t)row * DD);
        dst[lane] = src[lane];
        dst[lane + 32] = src[lane + 32];
    }
    if (out_codes && lane == 0) out_codes[row] = (float)idx;
}

// ---------------------------------------------------------------------------
extern "C" void kernel_launch(void* const* d_in, const int* in_sizes, int n_in,
                              void* d_out, int out_size) {
    const float* x = (const float*)d_in[1];
    const float* cent = (const float*)d_in[2];

    float* out = (float*)d_out;
    float* out_xhat = nullptr;
    float* out_codes = nullptr;
    const int XH = BQ * DD;
    if (out_size >= XH) {
        out_xhat = out;
        if (out_size >= XH + BQ) out_codes = out + XH;
    } else if (out_size >= BQ) {
        out_codes = out;
    }

    cudaFuncSetAttribute(main_kernel,
                         cudaFuncAttributeMaxDynamicSharedMemorySize, SMEM_TOTAL);

    init_kernel<<<(BQ + 255) / 256, 256>>>();
    csq_kernel<<<KK / 8, 256>>>(cent);
    cvt_cent_kernel<<<(KK * DD / 4) / 256, 256>>>(cent);
    cvt_x_kernel<<<(BQ * DD / 4) / 256, 256>>>(x);
    main_kernel<<<MAIN_GRID, NTHREADS, SMEM_TOTAL>>>();
    rescore_kernel<<<512, 256>>>(x, cent);
    finalize_kernel<<<BQ / 8, 256>>>(cent, out_xhat, out_codes);
}